// round 3
// baseline (speedup 1.0000x reference)
#include <cuda_runtime.h>
#include <cstdint>

// Problem constants
#define BATCH   32
#define HW      56
#define CCH     192
#define WS      7
#define NWIN1D  8
#define NW      49
#define BW      2048
#define HEADS   6
#define DH      32
#define MTOK    100352
#define QKV_N   576
#define NP      64          // padded tokens per window

// Scratch (device globals — allocation-free)
__device__ float g_xw[(size_t)BW * NW * CCH];
__device__ float g_qkv[(size_t)3 * BW * HEADS * NW * DH];
__device__ float g_att[(size_t)BW * NW * CCH];

__device__ __forceinline__ uint32_t f2tf32(float x) {
    uint32_t r;
    asm("cvt.rna.tf32.f32 %0, %1;" : "=r"(r) : "f"(x));
    return r;
}

__device__ __forceinline__ void mma_tf32(float c[4], const uint32_t a[4], const uint32_t b[2]) {
    asm volatile(
        "mma.sync.aligned.m16n8k8.row.col.f32.tf32.tf32.f32 "
        "{%0,%1,%2,%3}, {%4,%5,%6,%7}, {%8,%9}, {%0,%1,%2,%3};"
        : "+f"(c[0]), "+f"(c[1]), "+f"(c[2]), "+f"(c[3])
        : "r"(a[0]), "r"(a[1]), "r"(a[2]), "r"(a[3]), "r"(b[0]), "r"(b[1]));
}

// ---------------------------------------------------------------------------
// Kernel 1: LayerNorm + window partition. One warp per token.
// ---------------------------------------------------------------------------
__global__ void ln_partition_kernel(const float* __restrict__ x,
                                    const float* __restrict__ gamma) {
    int t    = blockIdx.x * 8 + (threadIdx.x >> 5);
    int lane = threadIdx.x & 31;
    const float* xp = x + (size_t)t * CCH;

    float v[6];
    float s = 0.f, sq = 0.f;
#pragma unroll
    for (int i = 0; i < 6; i++) {
        v[i] = xp[lane + 32 * i];
        s  += v[i];
        sq += v[i] * v[i];
    }
#pragma unroll
    for (int off = 16; off > 0; off >>= 1) {
        s  += __shfl_xor_sync(0xFFFFFFFFu, s,  off);
        sq += __shfl_xor_sync(0xFFFFFFFFu, sq, off);
    }
    float mu  = s  * (1.0f / CCH);
    float var = sq * (1.0f / CCH) - mu * mu;
    float rs  = rsqrtf(var + 1e-5f);

    int b  = t / 3136;
    int rc = t % 3136;
    int r  = rc / HW, c = rc % HW;
    int wr = r / WS, ir = r % WS;
    int wc = c / WS, ic = c % WS;
    int w  = (b * NWIN1D + wr) * NWIN1D + wc;
    int n  = ir * WS + ic;

    float* dst = g_xw + ((size_t)w * NW + n) * CCH;
#pragma unroll
    for (int i = 0; i < 6; i++) {
        int ch = lane + 32 * i;
        dst[ch] = (v[i] - mu) * rs * gamma[ch];
    }
}

// ---------------------------------------------------------------------------
// TF32 tensor-core GEMM (unchanged from R2): C = A[M,192] @ W[N,192]^T + bias
// ---------------------------------------------------------------------------
template <int EPI>
__global__ void __launch_bounds__(256) gemm_tf32_kernel(const float* __restrict__ A,
                                                        const float* __restrict__ W,
                                                        const float* __restrict__ bias,
                                                        float* __restrict__ out) {
    __shared__ uint32_t As[128][36];
    __shared__ uint32_t Bs[64][36];

    int tid  = threadIdx.x;
    int lane = tid & 31;
    int wid  = tid >> 5;
    int wm = wid & 3;
    int wn = wid >> 2;

    int bn = blockIdx.x;
    int bm = blockIdx.y;

    const float* Ag = A + (size_t)(bm * 128) * CCH;
    const float* Wg = W + (size_t)(bn * 64) * CCH;

    float acc[2][4][4] = {};

    for (int kt = 0; kt < CCH; kt += 32) {
#pragma unroll
        for (int i = 0; i < 4; i++) {
            int q = tid + i * 256;
            int row = q >> 3;
            int kq  = q & 7;
            float4 f = *(const float4*)(Ag + (size_t)row * CCH + kt + kq * 4);
            As[row][kq * 4 + 0] = f2tf32(f.x);
            As[row][kq * 4 + 1] = f2tf32(f.y);
            As[row][kq * 4 + 2] = f2tf32(f.z);
            As[row][kq * 4 + 3] = f2tf32(f.w);
        }
#pragma unroll
        for (int i = 0; i < 2; i++) {
            int q = tid + i * 256;
            int row = q >> 3;
            int kq  = q & 7;
            float4 f = *(const float4*)(Wg + (size_t)row * CCH + kt + kq * 4);
            Bs[row][kq * 4 + 0] = f2tf32(f.x);
            Bs[row][kq * 4 + 1] = f2tf32(f.y);
            Bs[row][kq * 4 + 2] = f2tf32(f.z);
            Bs[row][kq * 4 + 3] = f2tf32(f.w);
        }
        __syncthreads();

#pragma unroll
        for (int ks = 0; ks < 32; ks += 8) {
            uint32_t af[2][4];
            uint32_t bf[4][2];
#pragma unroll
            for (int mt = 0; mt < 2; mt++) {
                int row = wm * 32 + mt * 16 + (lane >> 2);
                int k   = ks + (lane & 3);
                af[mt][0] = As[row][k];
                af[mt][1] = As[row + 8][k];
                af[mt][2] = As[row][k + 4];
                af[mt][3] = As[row + 8][k + 4];
            }
#pragma unroll
            for (int nt = 0; nt < 4; nt++) {
                int col = wn * 32 + nt * 8 + (lane >> 2);
                int k   = ks + (lane & 3);
                bf[nt][0] = Bs[col][k];
                bf[nt][1] = Bs[col][k + 4];
            }
#pragma unroll
            for (int mt = 0; mt < 2; mt++)
#pragma unroll
                for (int nt = 0; nt < 4; nt++)
                    mma_tf32(acc[mt][nt], af[mt], bf[nt]);
        }
        __syncthreads();
    }

#pragma unroll
    for (int mt = 0; mt < 2; mt++) {
#pragma unroll
        for (int nt = 0; nt < 4; nt++) {
#pragma unroll
            for (int e = 0; e < 4; e++) {
                int m  = bm * 128 + wm * 32 + mt * 16 + (lane >> 2) + (e >> 1) * 8;
                int jc = bn * 64 + wn * 32 + nt * 8 + (lane & 3) * 2 + (e & 1);
                float val = acc[mt][nt][e] + bias[jc];
                if (EPI == 0) {
                    int w = m / NW, n = m % NW;
                    int s    = jc / CCH;
                    int rem  = jc % CCH;
                    int head = rem / DH;
                    int dd   = rem % DH;
                    g_qkv[(((size_t)s * BW + w) * HEADS + head) * (NW * DH) + n * DH + dd] = val;
                } else {
                    int w = m / NW, n = m % NW;
                    int b  = w / 64;
                    int wr = (w % 64) / NWIN1D;
                    int wc = w % NWIN1D;
                    int r  = wr * WS + n / WS;
                    int c  = wc * WS + n % WS;
                    size_t t = (size_t)b * 3136 + (size_t)r * HW + c;
                    out[t * CCH + jc] = val;
                }
            }
        }
    }
}

// ---------------------------------------------------------------------------
// Kernel 3: tensor-core attention per (window, head). 128 threads = 4 warps.
// QK^T and P@V via m16n8k8 tf32 MMA; softmax in registers.
// ---------------------------------------------------------------------------
#define QKP 40   // pitch (words) for q/k/v smem: banks 8g+j, conflict-free
#define PP  72   // pitch for P smem

__global__ void __launch_bounds__(128) attn_kernel(const float* __restrict__ rpb) {
    int w    = blockIdx.x;
    int head = blockIdx.y;
    int tid  = threadIdx.x;
    int lane = tid & 31;
    int wid  = tid >> 5;

    // qk region (2*NP*QKP = 5120 words) is reused for P (NP*PP = 4608 words)
    __shared__ uint32_t qkS[2 * NP * QKP];
    __shared__ uint32_t vS[NP * QKP];
    __shared__ float biasS[169];
    uint32_t* qS = qkS;
    uint32_t* kS = qkS + NP * QKP;
    uint32_t* pS = qkS;

    size_t base = ((size_t)w * HEADS + head) * (NW * DH);
    const float* qg = g_qkv + base;
    const float* kg = g_qkv + (size_t)BW * HEADS * NW * DH + base;
    const float* vg = g_qkv + (size_t)2 * BW * HEADS * NW * DH + base;

    const float scale = 0.17677669529663687f;  // 1/sqrt(32)

    // Load + convert q (pre-scaled), k, v; zero-pad rows 49..63
    for (int i = tid; i < NP * DH; i += 128) {
        int row = i >> 5, c = i & 31;
        float qv = 0.f, kv = 0.f, vv = 0.f;
        if (row < NW) {
            qv = qg[row * DH + c] * scale;
            kv = kg[row * DH + c];
            vv = vg[row * DH + c];
        }
        qS[row * QKP + c] = f2tf32(qv);
        kS[row * QKP + c] = f2tf32(kv);
        vS[row * QKP + c] = f2tf32(vv);
    }
    for (int i = tid; i < 169; i += 128) biasS[i] = rpb[i * HEADS + head];
    __syncthreads();

    // ---- QK^T: warp computes rows m0..m0+15 x cols 0..63 ----
    int m0 = wid * 16;
    float acc[8][4] = {};
#pragma unroll
    for (int ks = 0; ks < DH; ks += 8) {
        uint32_t af[4];
        int row = m0 + (lane >> 2);
        int kk  = ks + (lane & 3);
        af[0] = qS[row * QKP + kk];
        af[1] = qS[(row + 8) * QKP + kk];
        af[2] = qS[row * QKP + kk + 4];
        af[3] = qS[(row + 8) * QKP + kk + 4];
#pragma unroll
        for (int nt = 0; nt < 8; nt++) {
            uint32_t bf[2];
            int col = nt * 8 + (lane >> 2);
            bf[0] = kS[col * QKP + kk];
            bf[1] = kS[col * QKP + kk + 4];
            mma_tf32(acc[nt], af, bf);
        }
    }

    // ---- bias + masked softmax (rows r0 = m0+lane>>2, r1 = r0+8) ----
    int r0 = m0 + (lane >> 2);
    int r1 = r0 + 8;
    int r0c = r0 < NW ? r0 : NW - 1;
    int r1c = r1 < NW ? r1 : NW - 1;
    int ir0 = r0c / WS, ic0 = r0c % WS;
    int ir1 = r1c / WS, ic1 = r1c % WS;

    float mx0 = -1e30f, mx1 = -1e30f;
#pragma unroll
    for (int nt = 0; nt < 8; nt++) {
#pragma unroll
        for (int p = 0; p < 2; p++) {
            int col = nt * 8 + (lane & 3) * 2 + p;
            if (col < NW) {
                int jr = col / WS, jc = col % WS;
                acc[nt][p]     += biasS[(ir0 - jr + 6) * 13 + (ic0 - jc + 6)];
                acc[nt][2 + p] += biasS[(ir1 - jr + 6) * 13 + (ic1 - jc + 6)];
                mx0 = fmaxf(mx0, acc[nt][p]);
                mx1 = fmaxf(mx1, acc[nt][2 + p]);
            } else {
                acc[nt][p]     = -1e30f;
                acc[nt][2 + p] = -1e30f;
            }
        }
    }
    mx0 = fmaxf(mx0, __shfl_xor_sync(0xFFFFFFFFu, mx0, 1));
    mx0 = fmaxf(mx0, __shfl_xor_sync(0xFFFFFFFFu, mx0, 2));
    mx1 = fmaxf(mx1, __shfl_xor_sync(0xFFFFFFFFu, mx1, 1));
    mx1 = fmaxf(mx1, __shfl_xor_sync(0xFFFFFFFFu, mx1, 2));

    float sum0 = 0.f, sum1 = 0.f;
#pragma unroll
    for (int nt = 0; nt < 8; nt++) {
#pragma unroll
        for (int p = 0; p < 2; p++) {
            int col = nt * 8 + (lane & 3) * 2 + p;
            float e0 = (col < NW) ? __expf(acc[nt][p] - mx0) : 0.f;
            float e1 = (col < NW) ? __expf(acc[nt][2 + p] - mx1) : 0.f;
            acc[nt][p] = e0;
            acc[nt][2 + p] = e1;
            sum0 += e0;
            sum1 += e1;
        }
    }
    sum0 += __shfl_xor_sync(0xFFFFFFFFu, sum0, 1);
    sum0 += __shfl_xor_sync(0xFFFFFFFFu, sum0, 2);
    sum1 += __shfl_xor_sync(0xFFFFFFFFu, sum1, 1);
    sum1 += __shfl_xor_sync(0xFFFFFFFFu, sum1, 2);
    float inv0 = 1.0f / sum0;
    float inv1 = 1.0f / sum1;

    __syncthreads();   // all warps done reading qS/kS; safe to overwrite with P

    // store P (tf32) — each thread stores col pairs as uint2
#pragma unroll
    for (int nt = 0; nt < 8; nt++) {
        int col = nt * 8 + (lane & 3) * 2;
        uint2 v0 = { f2tf32(acc[nt][0] * inv0), f2tf32(acc[nt][1] * inv0) };
        uint2 v1 = { f2tf32(acc[nt][2] * inv1), f2tf32(acc[nt][3] * inv1) };
        *(uint2*)&pS[r0 * PP + col] = v0;
        *(uint2*)&pS[r1 * PP + col] = v1;
    }
    __syncthreads();

    // ---- AV: rows m0..m0+15 x dh 0..31 ----
    float acc2[4][4] = {};
#pragma unroll
    for (int ks = 0; ks < NP; ks += 8) {
        uint32_t af[4];
        int row = m0 + (lane >> 2);
        int kk  = ks + (lane & 3);
        af[0] = pS[row * PP + kk];
        af[1] = pS[(row + 8) * PP + kk];
        af[2] = pS[row * PP + kk + 4];
        af[3] = pS[(row + 8) * PP + kk + 4];
#pragma unroll
        for (int nt = 0; nt < 4; nt++) {
            uint32_t bf[2];
            int col = nt * 8 + (lane >> 2);
            bf[0] = vS[kk * QKP + col];
            bf[1] = vS[(kk + 4) * QKP + col];
            mma_tf32(acc2[nt], af, bf);
        }
    }

    // write out: g_att[(w*NW + m)*CCH + head*DH + dh]
    float* outp = g_att + (size_t)w * NW * CCH + head * DH;
#pragma unroll
    for (int nt = 0; nt < 4; nt++) {
        int col = nt * 8 + (lane & 3) * 2;
        if (r0 < NW) {
            float2 v0 = { acc2[nt][0], acc2[nt][1] };
            *(float2*)&outp[(size_t)r0 * CCH + col] = v0;
        }
        if (r1 < NW) {
            float2 v1 = { acc2[nt][2], acc2[nt][3] };
            *(float2*)&outp[(size_t)r1 * CCH + col] = v1;
        }
    }
}

// ---------------------------------------------------------------------------
extern "C" void kernel_launch(void* const* d_in, const int* in_sizes, int n_in,
                              void* d_out, int out_size) {
    const float* x      = (const float*)d_in[0];
    const float* gamma  = (const float*)d_in[1];
    const float* rpb    = (const float*)d_in[2];
    const float* qkv_w  = (const float*)d_in[3];
    const float* qkv_b  = (const float*)d_in[4];
    const float* proj_w = (const float*)d_in[5];
    const float* proj_b = (const float*)d_in[6];
    float* out = (float*)d_out;

    float* xw_ptr;  cudaGetSymbolAddress((void**)&xw_ptr, g_xw);
    float* att_ptr; cudaGetSymbolAddress((void**)&att_ptr, g_att);

    ln_partition_kernel<<<MTOK / 8, 256>>>(x, gamma);
    gemm_tf32_kernel<0><<<dim3(QKV_N / 64, MTOK / 128), 256>>>(xw_ptr, qkv_w, qkv_b, nullptr);
    attn_kernel<<<dim3(BW, HEADS), 128>>>(rpb);
    gemm_tf32_kernel<1><<<dim3(CCH / 64, MTOK / 128), 256>>>(att_ptr, proj_w, proj_b, out);
}

// round 4
// speedup vs baseline: 1.1821x; 1.1821x over previous
#include <cuda_runtime.h>
#include <cstdint>

#define BATCH   32
#define HW      56
#define CCH     192
#define WS      7
#define NW      49
#define BW      2048
#define HEADS   6
#define DH      32
#define MTOK    100352
#define QKV_N   576

// Scratch (device globals — allocation-free)
__device__ float2 g_stats[MTOK];                    // per-token (mu, rsig)
__device__ float  g_qkv[(size_t)MTOK * QKV_N];      // row-major [m][3C], window token order
__device__ float  g_att[(size_t)MTOK * CCH];        // row-major [m][C], window token order

__device__ __forceinline__ uint32_t f2tf32(float x) {
    uint32_t r;
    asm("cvt.rna.tf32.f32 %0, %1;" : "=r"(r) : "f"(x));
    return r;
}

__device__ __forceinline__ void mma_tf32(float c[4], const uint32_t a[4], const uint32_t b[2]) {
    asm volatile(
        "mma.sync.aligned.m16n8k8.row.col.f32.tf32.tf32.f32 "
        "{%0,%1,%2,%3}, {%4,%5,%6,%7}, {%8,%9}, {%0,%1,%2,%3};"
        : "+f"(c[0]), "+f"(c[1]), "+f"(c[2]), "+f"(c[3])
        : "r"(a[0]), "r"(a[1]), "r"(a[2]), "r"(a[3]), "r"(b[0]), "r"(b[1]));
}

// ---------------------------------------------------------------------------
// Kernel 1: LN statistics only. One warp per token, writes (mu, rsig).
// ---------------------------------------------------------------------------
__global__ void ln_stats_kernel(const float* __restrict__ x) {
    int t    = blockIdx.x * 8 + (threadIdx.x >> 5);
    int lane = threadIdx.x & 31;
    const float* xp = x + (size_t)t * CCH;

    float s = 0.f, sq = 0.f;
#pragma unroll
    for (int i = 0; i < 6; i++) {
        float v = xp[lane + 32 * i];
        s  += v;
        sq += v * v;
    }
#pragma unroll
    for (int off = 16; off > 0; off >>= 1) {
        s  += __shfl_xor_sync(0xFFFFFFFFu, s,  off);
        sq += __shfl_xor_sync(0xFFFFFFFFu, sq, off);
    }
    if (lane == 0) {
        float mu  = s * (1.0f / CCH);
        float var = sq * (1.0f / CCH) - mu * mu;
        g_stats[t] = make_float2(mu, rsqrtf(var + 1e-5f));
    }
}

// ---------------------------------------------------------------------------
// TF32 GEMM: C[M,N] = A[M,192] @ W[N,192]^T + bias
// BM=128, BN=64, BK=32, 256 threads (8 warps), warp tile 32x32.
// Paired-(k,k+4) smem layout -> LDS.64 fragment loads; register-staged prefetch.
// MODE 0: A = raw x with window remap + fused LayerNorm; C -> g_qkv row-major.
// MODE 1: A = g_att; C -> window-reverse scatter into out.
// ---------------------------------------------------------------------------
template <int MODE>
__global__ void __launch_bounds__(256) gemm_kernel(const float* __restrict__ A,
                                                   const float* __restrict__ gamma,
                                                   const float* __restrict__ W,
                                                   const float* __restrict__ bias,
                                                   float* __restrict__ out) {
    __shared__ uint32_t As[128 * 40];
    __shared__ uint32_t Bs[64 * 40];

    int tid  = threadIdx.x;
    int lane = tid & 31;
    int wid  = tid >> 5;
    int wm = wid & 3;
    int wn = wid >> 2;
    int bn = blockIdx.x;
    int bm = blockIdx.y;

    int kq = tid & 7;                 // which float4 of the 32-k slab
    int srow = tid >> 3;              // 0..31

    // Per-thread A-row setup (4 rows), with window remap + LN params for MODE 0
    const float* aptr[4];
    float amu[4], ars[4];
#pragma unroll
    for (int i = 0; i < 4; i++) {
        int row = srow + i * 32;
        int m   = bm * 128 + row;
        if (MODE == 0) {
            int w = m / NW, n = m % NW;
            int b  = w >> 6;
            int wr = (w & 63) >> 3;
            int wc = w & 7;
            int t  = b * 3136 + (wr * WS + n / WS) * HW + wc * WS + n % WS;
            aptr[i] = A + (size_t)t * CCH;
            float2 st = g_stats[t];
            amu[i] = st.x;
            ars[i] = st.y;
        } else {
            aptr[i] = A + (size_t)m * CCH;
        }
    }
    const float* bptr[2];
#pragma unroll
    for (int i = 0; i < 2; i++)
        bptr[i] = W + (size_t)(bn * 64 + srow + i * 32) * CCH;

    float4 Ar[4], Br[2];
    int pbase = (kq >> 1) * 8 + (kq & 1);   // permuted store base within row

    float acc[2][4][4] = {};

    // prologue: load tile 0
#pragma unroll
    for (int i = 0; i < 4; i++) Ar[i] = *(const float4*)(aptr[i] + kq * 4);
#pragma unroll
    for (int i = 0; i < 2; i++) Br[i] = *(const float4*)(bptr[i] + kq * 4);

    for (int kt = 0; kt < CCH; kt += 32) {
        // store staged tile into smem (LN + tf32 convert)
        {
            float4 gv;
            if (MODE == 0) gv = *(const float4*)(gamma + kt + kq * 4);
#pragma unroll
            for (int i = 0; i < 4; i++) {
                float4 f = Ar[i];
                if (MODE == 0) {
                    f.x = (f.x - amu[i]) * ars[i] * gv.x;
                    f.y = (f.y - amu[i]) * ars[i] * gv.y;
                    f.z = (f.z - amu[i]) * ars[i] * gv.z;
                    f.w = (f.w - amu[i]) * ars[i] * gv.w;
                }
                uint32_t* p = &As[(srow + i * 32) * 40 + pbase];
                p[0] = f2tf32(f.x); p[2] = f2tf32(f.y);
                p[4] = f2tf32(f.z); p[6] = f2tf32(f.w);
            }
#pragma unroll
            for (int i = 0; i < 2; i++) {
                float4 f = Br[i];
                uint32_t* p = &Bs[(srow + i * 32) * 40 + pbase];
                p[0] = f2tf32(f.x); p[2] = f2tf32(f.y);
                p[4] = f2tf32(f.z); p[6] = f2tf32(f.w);
            }
        }
        __syncthreads();

        // prefetch next tile into registers while MMAs run
        if (kt + 32 < CCH) {
#pragma unroll
            for (int i = 0; i < 4; i++) Ar[i] = *(const float4*)(aptr[i] + kt + 32 + kq * 4);
#pragma unroll
            for (int i = 0; i < 2; i++) Br[i] = *(const float4*)(bptr[i] + kt + 32 + kq * 4);
        }

#pragma unroll
        for (int ks = 0; ks < 32; ks += 8) {
            int off = ks + 2 * (lane & 3);
            uint32_t af[2][4];
            uint32_t bf[4][2];
#pragma unroll
            for (int mt = 0; mt < 2; mt++) {
                int r = wm * 32 + mt * 16 + (lane >> 2);
                uint2 lo = *(const uint2*)&As[r * 40 + off];
                uint2 hi = *(const uint2*)&As[(r + 8) * 40 + off];
                af[mt][0] = lo.x; af[mt][2] = lo.y;
                af[mt][1] = hi.x; af[mt][3] = hi.y;
            }
#pragma unroll
            for (int nt = 0; nt < 4; nt++) {
                int c = wn * 32 + nt * 8 + (lane >> 2);
                uint2 b2 = *(const uint2*)&Bs[c * 40 + off];
                bf[nt][0] = b2.x; bf[nt][1] = b2.y;
            }
#pragma unroll
            for (int mt = 0; mt < 2; mt++)
#pragma unroll
                for (int nt = 0; nt < 4; nt++)
                    mma_tf32(acc[mt][nt], af[mt], bf[nt]);
        }
        __syncthreads();
    }

    // Epilogue
#pragma unroll
    for (int nt = 0; nt < 4; nt++) {
        int jc = bn * 64 + wn * 32 + nt * 8 + (lane & 3) * 2;
        float2 bb = *(const float2*)&bias[jc];
#pragma unroll
        for (int mt = 0; mt < 2; mt++) {
#pragma unroll
            for (int h = 0; h < 2; h++) {
                int m = bm * 128 + wm * 32 + mt * 16 + (lane >> 2) + h * 8;
                float2 v = { acc[mt][nt][2 * h + 0] + bb.x,
                             acc[mt][nt][2 * h + 1] + bb.y };
                if (MODE == 0) {
                    *(float2*)&g_qkv[(size_t)m * QKV_N + jc] = v;
                } else {
                    int w = m / NW, n = m % NW;
                    int b  = w >> 6;
                    int wr = (w & 63) >> 3;
                    int wc = w & 7;
                    int r  = wr * WS + n / WS;
                    int c  = wc * WS + n % WS;
                    size_t t = (size_t)b * 3136 + (size_t)r * HW + c;
                    *(float2*)&out[t * CCH + jc] = v;
                }
            }
        }
    }
}

// ---------------------------------------------------------------------------
// Kernel 3: tensor-core attention per (window, head). 128 threads = 4 warps.
// 56-padded K/N dimension (7 n-tiles), 64-padded query rows.
// ---------------------------------------------------------------------------
#define QKP 40   // pitch for q/k/v smem
#define PP  72   // pitch for P smem
#define NPQ 64
#define NPK 56
#define NT  7    // 56/8 column tiles

__global__ void __launch_bounds__(128) attn_kernel(const float* __restrict__ rpb) {
    int w    = blockIdx.x;
    int head = blockIdx.y;
    int tid  = threadIdx.x;
    int lane = tid & 31;
    int wid  = tid >> 5;

    // q (64 rows) + k (56 rows) region reused for P (64 x PP)
    __shared__ uint32_t qkS[(NPQ + NPK) * QKP];
    __shared__ uint32_t vS[NPK * QKP];
    __shared__ float biasS[169];
    uint32_t* qS = qkS;
    uint32_t* kS = qkS + NPQ * QKP;
    uint32_t* pS = qkS;

    const float* qg = g_qkv + (size_t)w * NW * QKV_N + head * DH;
    const float* kg = qg + CCH;
    const float* vg = qg + 2 * CCH;

    const float scale = 0.17677669529663687f;  // 1/sqrt(32)

    for (int i = tid; i < NPQ * DH; i += 128) {
        int row = i >> 5, c = i & 31;
        float qv = 0.f;
        if (row < NW) qv = qg[(size_t)row * QKV_N + c] * scale;
        qS[row * QKP + c] = f2tf32(qv);
        if (row < NPK) {
            float kv = 0.f, vv = 0.f;
            if (row < NW) {
                kv = kg[(size_t)row * QKV_N + c];
                vv = vg[(size_t)row * QKV_N + c];
            }
            kS[row * QKP + c] = f2tf32(kv);
            vS[row * QKP + c] = f2tf32(vv);
        }
    }
    for (int i = tid; i < 169; i += 128) biasS[i] = rpb[i * HEADS + head];
    __syncthreads();

    // ---- QK^T: warp rows m0..m0+15 x cols 0..55 ----
    int m0 = wid * 16;
    float acc[NT][4] = {};
#pragma unroll
    for (int ks = 0; ks < DH; ks += 8) {
        uint32_t af[4];
        int row = m0 + (lane >> 2);
        int kk  = ks + (lane & 3);
        af[0] = qS[row * QKP + kk];
        af[1] = qS[(row + 8) * QKP + kk];
        af[2] = qS[row * QKP + kk + 4];
        af[3] = qS[(row + 8) * QKP + kk + 4];
#pragma unroll
        for (int nt = 0; nt < NT; nt++) {
            uint32_t bf[2];
            int col = nt * 8 + (lane >> 2);
            bf[0] = kS[col * QKP + kk];
            bf[1] = kS[col * QKP + kk + 4];
            mma_tf32(acc[nt], af, bf);
        }
    }

    // ---- bias + masked softmax ----
    int r0 = m0 + (lane >> 2);
    int r1 = r0 + 8;
    int r0c = r0 < NW ? r0 : NW - 1;
    int r1c = r1 < NW ? r1 : NW - 1;
    int ir0 = r0c / WS, ic0 = r0c % WS;
    int ir1 = r1c / WS, ic1 = r1c % WS;

    float mx0 = -1e30f, mx1 = -1e30f;
#pragma unroll
    for (int nt = 0; nt < NT; nt++) {
#pragma unroll
        for (int p = 0; p < 2; p++) {
            int col = nt * 8 + (lane & 3) * 2 + p;
            if (col < NW) {
                int jr = col / WS, jc = col % WS;
                acc[nt][p]     += biasS[(ir0 - jr + 6) * 13 + (ic0 - jc + 6)];
                acc[nt][2 + p] += biasS[(ir1 - jr + 6) * 13 + (ic1 - jc + 6)];
                mx0 = fmaxf(mx0, acc[nt][p]);
                mx1 = fmaxf(mx1, acc[nt][2 + p]);
            } else {
                acc[nt][p]     = -1e30f;
                acc[nt][2 + p] = -1e30f;
            }
        }
    }
    mx0 = fmaxf(mx0, __shfl_xor_sync(0xFFFFFFFFu, mx0, 1));
    mx0 = fmaxf(mx0, __shfl_xor_sync(0xFFFFFFFFu, mx0, 2));
    mx1 = fmaxf(mx1, __shfl_xor_sync(0xFFFFFFFFu, mx1, 1));
    mx1 = fmaxf(mx1, __shfl_xor_sync(0xFFFFFFFFu, mx1, 2));

    float sum0 = 0.f, sum1 = 0.f;
#pragma unroll
    for (int nt = 0; nt < NT; nt++) {
#pragma unroll
        for (int p = 0; p < 2; p++) {
            int col = nt * 8 + (lane & 3) * 2 + p;
            float e0 = (col < NW) ? __expf(acc[nt][p] - mx0) : 0.f;
            float e1 = (col < NW) ? __expf(acc[nt][2 + p] - mx1) : 0.f;
            acc[nt][p] = e0;
            acc[nt][2 + p] = e1;
            sum0 += e0;
            sum1 += e1;
        }
    }
    sum0 += __shfl_xor_sync(0xFFFFFFFFu, sum0, 1);
    sum0 += __shfl_xor_sync(0xFFFFFFFFu, sum0, 2);
    sum1 += __shfl_xor_sync(0xFFFFFFFFu, sum1, 1);
    sum1 += __shfl_xor_sync(0xFFFFFFFFu, sum1, 2);
    float inv0 = 1.0f / sum0;
    float inv1 = 1.0f / sum1;

    __syncthreads();   // done reading qS/kS; overwrite with P

#pragma unroll
    for (int nt = 0; nt < NT; nt++) {
        int col = nt * 8 + (lane & 3) * 2;
        uint2 v0 = { f2tf32(acc[nt][0] * inv0), f2tf32(acc[nt][1] * inv0) };
        uint2 v1 = { f2tf32(acc[nt][2] * inv1), f2tf32(acc[nt][3] * inv1) };
        *(uint2*)&pS[r0 * PP + col] = v0;
        *(uint2*)&pS[r1 * PP + col] = v1;
    }
    __syncthreads();

    // ---- AV: rows m0..m0+15 x dh 0..31, K = 56 ----
    float acc2[4][4] = {};
#pragma unroll
    for (int ks = 0; ks < NPK; ks += 8) {
        uint32_t af[4];
        int row = m0 + (lane >> 2);
        int kk  = ks + (lane & 3);
        af[0] = pS[row * PP + kk];
        af[1] = pS[(row + 8) * PP + kk];
        af[2] = pS[row * PP + kk + 4];
        af[3] = pS[(row + 8) * PP + kk + 4];
#pragma unroll
        for (int nt = 0; nt < 4; nt++) {
            uint32_t bf[2];
            int col = nt * 8 + (lane >> 2);
            bf[0] = vS[kk * QKP + col];
            bf[1] = vS[(kk + 4) * QKP + col];
            mma_tf32(acc2[nt], af, bf);
        }
    }

    float* outp = g_att + (size_t)w * NW * CCH + head * DH;
#pragma unroll
    for (int nt = 0; nt < 4; nt++) {
        int col = nt * 8 + (lane & 3) * 2;
        if (r0 < NW) {
            float2 v0 = { acc2[nt][0], acc2[nt][1] };
            *(float2*)&outp[(size_t)r0 * CCH + col] = v0;
        }
        if (r1 < NW) {
            float2 v1 = { acc2[nt][2], acc2[nt][3] };
            *(float2*)&outp[(size_t)r1 * CCH + col] = v1;
        }
    }
}

// ---------------------------------------------------------------------------
extern "C" void kernel_launch(void* const* d_in, const int* in_sizes, int n_in,
                              void* d_out, int out_size) {
    const float* x      = (const float*)d_in[0];
    const float* gamma  = (const float*)d_in[1];
    const float* rpb    = (const float*)d_in[2];
    const float* qkv_w  = (const float*)d_in[3];
    const float* qkv_b  = (const float*)d_in[4];
    const float* proj_w = (const float*)d_in[5];
    const float* proj_b = (const float*)d_in[6];
    float* out = (float*)d_out;

    float* att_ptr; cudaGetSymbolAddress((void**)&att_ptr, g_att);

    ln_stats_kernel<<<MTOK / 8, 256>>>(x);
    gemm_kernel<0><<<dim3(QKV_N / 64, MTOK / 128), 256>>>(x, gamma, qkv_w, qkv_b, nullptr);
    attn_kernel<<<dim3(BW, HEADS), 128>>>(rpb);
    gemm_kernel<1><<<dim3(CCH / 64, MTOK / 128), 256>>>(att_ptr, nullptr, proj_w, proj_b, out);
}

// round 6
// speedup vs baseline: 1.4581x; 1.2335x over previous
#include <cuda_runtime.h>
#include <cstdint>

#define BATCH   32
#define HW      56
#define CCH     192
#define WS      7
#define NW      49
#define BW      2048
#define HEADS   6
#define DH      32
#define MTOK    100352
#define QKV_N   576

// Scratch (device globals — allocation-free)
__device__ float2 g_stats[MTOK];
__device__ float  g_qkv[(size_t)MTOK * QKV_N];   // row-major [m][576], window token order
__device__ float  g_att[(size_t)MTOK * CCH];     // row-major [m][192], window token order

__device__ __forceinline__ uint32_t f2tf32(float x) {
    uint32_t r;
    asm("cvt.rna.tf32.f32 %0, %1;" : "=r"(r) : "f"(x));
    return r;
}

__device__ __forceinline__ void mma_tf32(float c[4], const uint32_t a[4], const uint32_t b[2]) {
    asm volatile(
        "mma.sync.aligned.m16n8k8.row.col.f32.tf32.tf32.f32 "
        "{%0,%1,%2,%3}, {%4,%5,%6,%7}, {%8,%9}, {%0,%1,%2,%3};"
        : "+f"(c[0]), "+f"(c[1]), "+f"(c[2]), "+f"(c[3])
        : "r"(a[0]), "r"(a[1]), "r"(a[2]), "r"(a[3]), "r"(b[0]), "r"(b[1]));
}

// ---------------------------------------------------------------------------
// Kernel 1: LN statistics only.
// ---------------------------------------------------------------------------
__global__ void ln_stats_kernel(const float* __restrict__ x) {
    int t    = blockIdx.x * 8 + (threadIdx.x >> 5);
    int lane = threadIdx.x & 31;
    const float* xp = x + (size_t)t * CCH;

    float s = 0.f, sq = 0.f;
#pragma unroll
    for (int i = 0; i < 6; i++) {
        float v = xp[lane + 32 * i];
        s  += v;
        sq += v * v;
    }
#pragma unroll
    for (int off = 16; off > 0; off >>= 1) {
        s  += __shfl_xor_sync(0xFFFFFFFFu, s,  off);
        sq += __shfl_xor_sync(0xFFFFFFFFu, sq, off);
    }
    if (lane == 0) {
        float mu  = s * (1.0f / CCH);
        float var = sq * (1.0f / CCH) - mu * mu;
        g_stats[t] = make_float2(mu, rsqrtf(var + 1e-5f));
    }
}

// ---------------------------------------------------------------------------
// TF32 GEMM, double-buffered smem, ONE sync per k-tile.
// BM=128, BN=64, BK=32, 256 threads (8 warps), warp tile 32x32.
// MODE 0: A = raw x + window remap + fused LN; C -> g_qkv row-major.
// MODE 1: A = g_att; C -> window-reverse scatter into out.
// Buffer layout (dynamic smem words): buf b at b*7680: A 128*40, B 64*40.
// ---------------------------------------------------------------------------
#define ABUF 5120
#define BUFW 7680
#define GEMM_SMEM (2 * BUFW * 4)

template <int MODE>
__global__ void __launch_bounds__(256) gemm_kernel(const float* __restrict__ A,
                                                   const float* __restrict__ gamma,
                                                   const float* __restrict__ W,
                                                   const float* __restrict__ bias,
                                                   float* __restrict__ out) {
    extern __shared__ uint32_t sm[];

    int tid  = threadIdx.x;
    int lane = tid & 31;
    int wid  = tid >> 5;
    int wm = wid & 3;
    int wn = wid >> 2;
    int bn = blockIdx.x;
    int bm = blockIdx.y;

    int kq   = tid & 7;      // which float4 of the 32-k slab
    int srow = tid >> 3;     // 0..31

    // Per-thread A-row setup (4 rows), window remap + LN params for MODE 0
    const float* aptr[4];
    float amu[4], ars[4];
#pragma unroll
    for (int i = 0; i < 4; i++) {
        int row = srow + i * 32;
        int m   = bm * 128 + row;
        if (MODE == 0) {
            int w = m / NW, n = m % NW;
            int b  = w >> 6;
            int wr = (w & 63) >> 3;
            int wc = w & 7;
            int t  = b * 3136 + (wr * WS + n / WS) * HW + wc * WS + n % WS;
            aptr[i] = A + (size_t)t * CCH;
            float2 st = g_stats[t];
            amu[i] = st.x;
            ars[i] = st.y;
        } else {
            aptr[i] = A + (size_t)(bm * 128 + row) * CCH;
        }
    }
    const float* bptr[2];
#pragma unroll
    for (int i = 0; i < 2; i++)
        bptr[i] = W + (size_t)(bn * 64 + srow + i * 32) * CCH;

    float4 Ar[4], Br[2];
    int pbase = (kq >> 1) * 8 + (kq & 1);   // permuted store base

    float acc[2][4][4] = {};

    // -------- prologue: load + store tile 0 into buf0 --------
#pragma unroll
    for (int i = 0; i < 4; i++) Ar[i] = *(const float4*)(aptr[i] + kq * 4);
#pragma unroll
    for (int i = 0; i < 2; i++) Br[i] = *(const float4*)(bptr[i] + kq * 4);
    {
        float4 gv;
        if (MODE == 0) gv = *(const float4*)(gamma + kq * 4);
#pragma unroll
        for (int i = 0; i < 4; i++) {
            float4 f = Ar[i];
            if (MODE == 0) {
                f.x = (f.x - amu[i]) * ars[i] * gv.x;
                f.y = (f.y - amu[i]) * ars[i] * gv.y;
                f.z = (f.z - amu[i]) * ars[i] * gv.z;
                f.w = (f.w - amu[i]) * ars[i] * gv.w;
            }
            uint32_t* p = &sm[(srow + i * 32) * 40 + pbase];
            p[0] = f2tf32(f.x); p[2] = f2tf32(f.y);
            p[4] = f2tf32(f.z); p[6] = f2tf32(f.w);
        }
#pragma unroll
        for (int i = 0; i < 2; i++) {
            float4 f = Br[i];
            uint32_t* p = &sm[ABUF + (srow + i * 32) * 40 + pbase];
            p[0] = f2tf32(f.x); p[2] = f2tf32(f.y);
            p[4] = f2tf32(f.z); p[6] = f2tf32(f.w);
        }
    }
    __syncthreads();

    // -------- main loop: one sync per kt --------
#pragma unroll
    for (int kt = 0; kt < 6; kt++) {
        // issue global loads for next tile (latency hidden by MMAs below)
        if (kt < 5) {
            int k = (kt + 1) * 32;
#pragma unroll
            for (int i = 0; i < 4; i++) Ar[i] = *(const float4*)(aptr[i] + k + kq * 4);
#pragma unroll
            for (int i = 0; i < 2; i++) Br[i] = *(const float4*)(bptr[i] + k + kq * 4);
        }

        // compute current buffer
        const uint32_t* Ac = sm + (kt & 1) * BUFW;
        const uint32_t* Bc = Ac + ABUF;
#pragma unroll
        for (int ks = 0; ks < 32; ks += 8) {
            int off = ks + 2 * (lane & 3);
            uint32_t af[2][4];
            uint32_t bf[4][2];
#pragma unroll
            for (int mt = 0; mt < 2; mt++) {
                int r = wm * 32 + mt * 16 + (lane >> 2);
                uint2 lo = *(const uint2*)&Ac[r * 40 + off];
                uint2 hi = *(const uint2*)&Ac[(r + 8) * 40 + off];
                af[mt][0] = lo.x; af[mt][2] = lo.y;
                af[mt][1] = hi.x; af[mt][3] = hi.y;
            }
#pragma unroll
            for (int nt = 0; nt < 4; nt++) {
                int c = wn * 32 + nt * 8 + (lane >> 2);
                uint2 b2 = *(const uint2*)&Bc[c * 40 + off];
                bf[nt][0] = b2.x; bf[nt][1] = b2.y;
            }
#pragma unroll
            for (int mt = 0; mt < 2; mt++)
#pragma unroll
                for (int nt = 0; nt < 4; nt++)
                    mma_tf32(acc[mt][nt], af[mt], bf[nt]);
        }

        // store next tile into the other buffer
        if (kt < 5) {
            uint32_t* An = sm + ((kt + 1) & 1) * BUFW;
            uint32_t* Bn = An + ABUF;
            float4 gv;
            if (MODE == 0) gv = *(const float4*)(gamma + (kt + 1) * 32 + kq * 4);
#pragma unroll
            for (int i = 0; i < 4; i++) {
                float4 f = Ar[i];
                if (MODE == 0) {
                    f.x = (f.x - amu[i]) * ars[i] * gv.x;
                    f.y = (f.y - amu[i]) * ars[i] * gv.y;
                    f.z = (f.z - amu[i]) * ars[i] * gv.z;
                    f.w = (f.w - amu[i]) * ars[i] * gv.w;
                }
                uint32_t* p = &An[(srow + i * 32) * 40 + pbase];
                p[0] = f2tf32(f.x); p[2] = f2tf32(f.y);
                p[4] = f2tf32(f.z); p[6] = f2tf32(f.w);
            }
#pragma unroll
            for (int i = 0; i < 2; i++) {
                float4 f = Br[i];
                uint32_t* p = &Bn[(srow + i * 32) * 40 + pbase];
                p[0] = f2tf32(f.x); p[2] = f2tf32(f.y);
                p[4] = f2tf32(f.z); p[6] = f2tf32(f.w);
            }
        }
        __syncthreads();
    }

    // -------- epilogue --------
#pragma unroll
    for (int nt = 0; nt < 4; nt++) {
        int jc = bn * 64 + wn * 32 + nt * 8 + (lane & 3) * 2;
        float2 bb = *(const float2*)&bias[jc];
#pragma unroll
        for (int mt = 0; mt < 2; mt++) {
#pragma unroll
            for (int h = 0; h < 2; h++) {
                int m = bm * 128 + wm * 32 + mt * 16 + (lane >> 2) + h * 8;
                float2 v = { acc[mt][nt][2 * h + 0] + bb.x,
                             acc[mt][nt][2 * h + 1] + bb.y };
                if (MODE == 0) {
                    *(float2*)&g_qkv[(size_t)m * QKV_N + jc] = v;
                } else {
                    int w = m / NW, n = m % NW;
                    int b  = w >> 6;
                    int wr = (w & 63) >> 3;
                    int wc = w & 7;
                    int r  = wr * WS + n / WS;
                    int c  = wc * WS + n % WS;
                    size_t t = (size_t)b * 3136 + (size_t)r * HW + c;
                    *(float2*)&out[t * CCH + jc] = v;
                }
            }
        }
    }
}

// ---------------------------------------------------------------------------
// Kernel 3: tensor-core attention per (window, head). 128 threads = 4 warps.
// Vectorized float4 q/k/v loads.
// ---------------------------------------------------------------------------
#define QKP 40
#define PP  72
#define NPQ 64
#define NPK 56
#define NT  7

__global__ void __launch_bounds__(128) attn_kernel(const float* __restrict__ rpb) {
    int w    = blockIdx.x;
    int head = blockIdx.y;
    int tid  = threadIdx.x;
    int lane = tid & 31;
    int wid  = tid >> 5;

    __shared__ uint32_t qkS[(NPQ + NPK) * QKP];
    __shared__ uint32_t vS[NPK * QKP];
    __shared__ float biasS[169];
    uint32_t* qS = qkS;
    uint32_t* kS = qkS + NPQ * QKP;
    uint32_t* pS = qkS;

    const float* qg = g_qkv + (size_t)w * NW * QKV_N + head * DH;
    const float* kg = qg + CCH;
    const float* vg = qg + 2 * CCH;

    const float scale = 0.17677669529663687f;

    // Vectorized loads: 2 threads/row, 4 float4 each.
    {
        int row = tid >> 1;
        int c0  = (tid & 1) * 16;
        if (row < NW) {
            const float* qr = qg + (size_t)row * QKV_N;
#pragma unroll
            for (int j = 0; j < 4; j++) {
                float4 f = *(const float4*)(qr + c0 + j * 4);
                uint4 u = { f2tf32(f.x * scale), f2tf32(f.y * scale),
                            f2tf32(f.z * scale), f2tf32(f.w * scale) };
                *(uint4*)&qS[row * QKP + c0 + j * 4] = u;
            }
            const float* kr = kg + (size_t)row * QKV_N;
            const float* vr = vg + (size_t)row * QKV_N;
#pragma unroll
            for (int j = 0; j < 4; j++) {
                float4 f = *(const float4*)(kr + c0 + j * 4);
                uint4 u = { f2tf32(f.x), f2tf32(f.y), f2tf32(f.z), f2tf32(f.w) };
                *(uint4*)&kS[row * QKP + c0 + j * 4] = u;
                float4 g = *(const float4*)(vr + c0 + j * 4);
                uint4 uv = { f2tf32(g.x), f2tf32(g.y), f2tf32(g.z), f2tf32(g.w) };
                *(uint4*)&vS[row * QKP + c0 + j * 4] = uv;
            }
        } else {
            uint4 z = { 0, 0, 0, 0 };
#pragma unroll
            for (int j = 0; j < 4; j++)
                *(uint4*)&qS[row * QKP + c0 + j * 4] = z;
            if (row < NPK) {
#pragma unroll
                for (int j = 0; j < 4; j++) {
                    *(uint4*)&kS[row * QKP + c0 + j * 4] = z;
                    *(uint4*)&vS[row * QKP + c0 + j * 4] = z;
                }
            }
        }
    }
    for (int i = tid; i < 169; i += 128) biasS[i] = rpb[i * HEADS + head];
    __syncthreads();

    int m0 = wid * 16;
    float acc[NT][4] = {};
#pragma unroll
    for (int ks = 0; ks < DH; ks += 8) {
        uint32_t af[4];
        int row = m0 + (lane >> 2);
        int kk  = ks + (lane & 3);
        af[0] = qS[row * QKP + kk];
        af[1] = qS[(row + 8) * QKP + kk];
        af[2] = qS[row * QKP + kk + 4];
        af[3] = qS[(row + 8) * QKP + kk + 4];
#pragma unroll
        for (int nt = 0; nt < NT; nt++) {
            uint32_t bf[2];
            int col = nt * 8 + (lane >> 2);
            bf[0] = kS[col * QKP + kk];
            bf[1] = kS[col * QKP + kk + 4];
            mma_tf32(acc[nt], af, bf);
        }
    }

    int r0 = m0 + (lane >> 2);
    int r1 = r0 + 8;
    int r0c = r0 < NW ? r0 : NW - 1;
    int r1c = r1 < NW ? r1 : NW - 1;
    int ir0 = r0c / WS, ic0 = r0c % WS;
    int ir1 = r1c / WS, ic1 = r1c % WS;

    float mx0 = -1e30f, mx1 = -1e30f;
#pragma unroll
    for (int nt = 0; nt < NT; nt++) {
#pragma unroll
        for (int p = 0; p < 2; p++) {
            int col = nt * 8 + (lane & 3) * 2 + p;
            if (col < NW) {
                int jr = col / WS, jc = col % WS;
                acc[nt][p]     += biasS[(ir0 - jr + 6) * 13 + (ic0 - jc + 6)];
                acc[nt][2 + p] += biasS[(ir1 - jr + 6) * 13 + (ic1 - jc + 6)];
                mx0 = fmaxf(mx0, acc[nt][p]);
                mx1 = fmaxf(mx1, acc[nt][2 + p]);
            } else {
                acc[nt][p]     = -1e30f;
                acc[nt][2 + p] = -1e30f;
            }
        }
    }
    mx0 = fmaxf(mx0, __shfl_xor_sync(0xFFFFFFFFu, mx0, 1));
    mx0 = fmaxf(mx0, __shfl_xor_sync(0xFFFFFFFFu, mx0, 2));
    mx1 = fmaxf(mx1, __shfl_xor_sync(0xFFFFFFFFu, mx1, 1));
    mx1 = fmaxf(mx1, __shfl_xor_sync(0xFFFFFFFFu, mx1, 2));

    float sum0 = 0.f, sum1 = 0.f;
#pragma unroll
    for (int nt = 0; nt < NT; nt++) {
#pragma unroll
        for (int p = 0; p < 2; p++) {
            int col = nt * 8 + (lane & 3) * 2 + p;
            float e0 = (col < NW) ? __expf(acc[nt][p] - mx0) : 0.f;
            float e1 = (col < NW) ? __expf(acc[nt][2 + p] - mx1) : 0.f;
            acc[nt][p] = e0;
            acc[nt][2 + p] = e1;
            sum0 += e0;
            sum1 += e1;
        }
    }
    sum0 += __shfl_xor_sync(0xFFFFFFFFu, sum0, 1);
    sum0 += __shfl_xor_sync(0xFFFFFFFFu, sum0, 2);
    sum1 += __shfl_xor_sync(0xFFFFFFFFu, sum1, 1);
    sum1 += __shfl_xor_sync(0xFFFFFFFFu, sum1, 2);
    float inv0 = 1.0f / sum0;
    float inv1 = 1.0f / sum1;

    __syncthreads();

#pragma unroll
    for (int nt = 0; nt < NT; nt++) {
        int col = nt * 8 + (lane & 3) * 2;
        uint2 v0 = { f2tf32(acc[nt][0] * inv0), f2tf32(acc[nt][1] * inv0) };
        uint2 v1 = { f2tf32(acc[nt][2] * inv1), f2tf32(acc[nt][3] * inv1) };
        *(uint2*)&pS[r0 * PP + col] = v0;
        *(uint2*)&pS[r1 * PP + col] = v1;
    }
    __syncthreads();

    float acc2[4][4] = {};
#pragma unroll
    for (int ks = 0; ks < NPK; ks += 8) {
        uint32_t af[4];
        int row = m0 + (lane >> 2);
        int kk  = ks + (lane & 3);
        af[0] = pS[row * PP + kk];
        af[1] = pS[(row + 8) * PP + kk];
        af[2] = pS[row * PP + kk + 4];
        af[3] = pS[(row + 8) * PP + kk + 4];
#pragma unroll
        for (int nt = 0; nt < 4; nt++) {
            uint32_t bf[2];
            int col = nt * 8 + (lane >> 2);
            bf[0] = vS[kk * QKP + col];
            bf[1] = vS[(kk + 4) * QKP + col];
            mma_tf32(acc2[nt], af, bf);
        }
    }

    float* outp = g_att + (size_t)w * NW * CCH + head * DH;
#pragma unroll
    for (int nt = 0; nt < 4; nt++) {
        int col = nt * 8 + (lane & 3) * 2;
        if (r0 < NW) {
            float2 v0 = { acc2[nt][0], acc2[nt][1] };
            *(float2*)&outp[(size_t)r0 * CCH + col] = v0;
        }
        if (r1 < NW) {
            float2 v1 = { acc2[nt][2], acc2[nt][3] };
            *(float2*)&outp[(size_t)r1 * CCH + col] = v1;
        }
    }
}

// ---------------------------------------------------------------------------
extern "C" void kernel_launch(void* const* d_in, const int* in_sizes, int n_in,
                              void* d_out, int out_size) {
    const float* x      = (const float*)d_in[0];
    const float* gamma  = (const float*)d_in[1];
    const float* rpb    = (const float*)d_in[2];
    const float* qkv_w  = (const float*)d_in[3];
    const float* qkv_b  = (const float*)d_in[4];
    const float* proj_w = (const float*)d_in[5];
    const float* proj_b = (const float*)d_in[6];
    float* out = (float*)d_out;

    float* att_ptr; cudaGetSymbolAddress((void**)&att_ptr, g_att);

    cudaFuncSetAttribute(gemm_kernel<0>, cudaFuncAttributeMaxDynamicSharedMemorySize, GEMM_SMEM);
    cudaFuncSetAttribute(gemm_kernel<1>, cudaFuncAttributeMaxDynamicSharedMemorySize, GEMM_SMEM);

    ln_stats_kernel<<<MTOK / 8, 256>>>(x);
    gemm_kernel<0><<<dim3(QKV_N / 64, MTOK / 128), 256, GEMM_SMEM>>>(x, gamma, qkv_w, qkv_b, nullptr);
    attn_kernel<<<dim3(BW, HEADS), 128>>>(rpb);
    gemm_kernel<1><<<dim3(CCH / 64, MTOK / 128), 256, GEMM_SMEM>>>(att_ptr, nullptr, proj_w, proj_b, out);
}

// round 7
// speedup vs baseline: 2.0839x; 1.4293x over previous
#include <cuda_runtime.h>
#include <cstdint>

#define BATCH   32
#define HW      56
#define CCH     192
#define WS      7
#define NW      49
#define NWIN    2048
#define HEADS   6
#define DH      32
#define MTOK    100352
#define QKV_N   576

// Scratch (device globals — allocation-free)
__device__ uint32_t g_xw[(size_t)MTOK * CCH];     // LN'd, window-ordered, tf32 k-permuted
__device__ float    g_qkv[(size_t)MTOK * QKV_N];  // fp32 row-major [m][576]
__device__ uint32_t g_att[(size_t)MTOK * CCH];    // attn out, tf32 k-permuted
__device__ uint32_t g_wq[(size_t)QKV_N * CCH];    // qkv_w tf32 k-permuted
__device__ uint32_t g_wp[(size_t)CCH * CCH];      // proj_w tf32 k-permuted

__device__ __forceinline__ uint32_t f2tf32(float x) {
    uint32_t r;
    asm("cvt.rna.tf32.f32 %0, %1;" : "=r"(r) : "f"(x));
    return r;
}
__device__ __forceinline__ void mma_tf32(float c[4], const uint32_t a[4], const uint32_t b[2]) {
    asm volatile(
        "mma.sync.aligned.m16n8k8.row.col.f32.tf32.tf32.f32 "
        "{%0,%1,%2,%3}, {%4,%5,%6,%7}, {%8,%9}, {%0,%1,%2,%3};"
        : "+f"(c[0]), "+f"(c[1]), "+f"(c[2]), "+f"(c[3])
        : "r"(a[0]), "r"(a[1]), "r"(a[2]), "r"(a[3]), "r"(b[0]), "r"(b[1]));
}
__device__ __forceinline__ uint32_t smem_u32(const void* p) {
    uint32_t a;
    asm("{ .reg .u64 t; cvta.to.shared.u64 t, %1; cvt.u32.u64 %0, t; }" : "=r"(a) : "l"(p));
    return a;
}
__device__ __forceinline__ void cp16(uint32_t s, const void* g) {
    asm volatile("cp.async.cg.shared.global [%0], [%1], 16;" :: "r"(s), "l"(g));
}
#define CP_COMMIT() asm volatile("cp.async.commit_group;" ::: "memory")
#define CP_WAIT0()  asm volatile("cp.async.wait_group 0;" ::: "memory")

// k-permutation within a 32-k slab: pairs (k, k+4) adjacent -> LDS.64 frags
__device__ __forceinline__ int pos32(int k) {
    return (k & 24) + ((k & 3) << 1) + ((k >> 2) & 1);
}

// ---------------------------------------------------------------------------
// Kernel 0: weight prep — convert + k-permute.
// ---------------------------------------------------------------------------
__global__ void prep_w_kernel(const float* __restrict__ src, uint32_t* __restrict__ dst, int n) {
    int idx = blockIdx.x * 256 + threadIdx.x;
    if (idx < n) {
        int r = idx / CCH, k = idx % CCH;
        dst[(size_t)r * CCH + (k & ~31) + pos32(k & 31)] = f2tf32(src[idx]);
    }
}

// ---------------------------------------------------------------------------
// Kernel 1: LayerNorm + window partition + tf32 convert + k-permute.
// One warp per token.
// ---------------------------------------------------------------------------
__global__ void ln_kernel(const float* __restrict__ x, const float* __restrict__ gamma) {
    int t    = blockIdx.x * 8 + (threadIdx.x >> 5);
    int lane = threadIdx.x & 31;
    const float* xp = x + (size_t)t * CCH;

    float v[6];
    float s = 0.f, sq = 0.f;
#pragma unroll
    for (int i = 0; i < 6; i++) {
        v[i] = xp[lane + 32 * i];
        s  += v[i];
        sq += v[i] * v[i];
    }
#pragma unroll
    for (int off = 16; off > 0; off >>= 1) {
        s  += __shfl_xor_sync(0xFFFFFFFFu, s,  off);
        sq += __shfl_xor_sync(0xFFFFFFFFu, sq, off);
    }
    float mu  = s * (1.0f / CCH);
    float var = sq * (1.0f / CCH) - mu * mu;
    float rs  = rsqrtf(var + 1e-5f);

    int b  = t / 3136;
    int rc = t % 3136;
    int r  = rc / HW, c = rc % HW;
    int w  = (b * 8 + r / WS) * 8 + c / WS;
    int n  = (r % WS) * WS + (c % WS);

    uint32_t* dst = g_xw + ((size_t)w * NW + n) * CCH + pos32(lane);
#pragma unroll
    for (int i = 0; i < 6; i++)
        dst[32 * i] = f2tf32((v[i] - mu) * rs * gamma[lane + 32 * i]);
}

// ---------------------------------------------------------------------------
// TF32 GEMM: BM=256, BN=64, BK=32. 128 threads = 4 warps, warp tile 64x64.
// Pre-converted/permuted operands, cp.async double buffer, pitch-40 rows.
// MODE 0: C -> g_qkv fp32 row-major.  MODE 1: C -> window-reverse out.
// ---------------------------------------------------------------------------
#define PITCH  40
#define AWRD   (256 * PITCH)          // 10240 words
#define BWRD   (64 * PITCH)           // 2560 words
#define BUFWRD (AWRD + BWRD)          // 12800 words
#define GSMEM  (2 * BUFWRD * 4)       // 102400 bytes

template <int MODE>
__global__ void __launch_bounds__(128) gemm_tc_kernel(const uint32_t* __restrict__ A,
                                                      const uint32_t* __restrict__ Wt,
                                                      const float* __restrict__ bias,
                                                      float* __restrict__ out) {
    extern __shared__ uint32_t sm[];
    uint32_t sb = smem_u32(sm);

    int tid  = threadIdx.x;
    int lane = tid & 31;
    int wid  = tid >> 5;
    int bn = blockIdx.x;
    int bm = blockIdx.y;

    const uint32_t* Ag = A  + (size_t)(bm * 256) * CCH;
    const uint32_t* Bg = Wt + (size_t)(bn * 64) * CCH;

    float acc[4][8][4] = {};

    // ---- issue tile 0 ----
    {
        uint32_t ab = sb;
#pragma unroll
        for (int i = 0; i < 16; i++) {
            int q = i * 128 + tid;
            int row = q >> 3, cs = q & 7;
            cp16(ab + (row * PITCH + cs * 4) * 4, Ag + (size_t)row * CCH + cs * 4);
        }
        uint32_t bb = sb + AWRD * 4;
#pragma unroll
        for (int i = 0; i < 4; i++) {
            int q = i * 128 + tid;
            int row = q >> 3, cs = q & 7;
            cp16(bb + (row * PITCH + cs * 4) * 4, Bg + (size_t)row * CCH + cs * 4);
        }
        CP_COMMIT();
    }

#pragma unroll
    for (int kt = 0; kt < 6; kt++) {
        CP_WAIT0();
        __syncthreads();

        if (kt < 5) {
            int buf = (kt + 1) & 1;
            int ko  = (kt + 1) * 32;
            uint32_t ab = sb + buf * BUFWRD * 4;
#pragma unroll
            for (int i = 0; i < 16; i++) {
                int q = i * 128 + tid;
                int row = q >> 3, cs = q & 7;
                cp16(ab + (row * PITCH + cs * 4) * 4, Ag + (size_t)row * CCH + ko + cs * 4);
            }
            uint32_t bb = ab + AWRD * 4;
#pragma unroll
            for (int i = 0; i < 4; i++) {
                int q = i * 128 + tid;
                int row = q >> 3, cs = q & 7;
                cp16(bb + (row * PITCH + cs * 4) * 4, Bg + (size_t)row * CCH + ko + cs * 4);
            }
            CP_COMMIT();
        }

        const uint32_t* Ab = sm + (kt & 1) * BUFWRD;
        const uint32_t* Bb = Ab + AWRD;
#pragma unroll
        for (int ks = 0; ks < 32; ks += 8) {
            int off = ks + 2 * (lane & 3);
            uint32_t af[4][4];
            uint32_t bf[8][2];
#pragma unroll
            for (int mt = 0; mt < 4; mt++) {
                int r = wid * 64 + mt * 16 + (lane >> 2);
                uint2 lo = *(const uint2*)&Ab[r * PITCH + off];
                uint2 hi = *(const uint2*)&Ab[(r + 8) * PITCH + off];
                af[mt][0] = lo.x; af[mt][2] = lo.y;
                af[mt][1] = hi.x; af[mt][3] = hi.y;
            }
#pragma unroll
            for (int nt = 0; nt < 8; nt++) {
                int c = nt * 8 + (lane >> 2);
                uint2 b2 = *(const uint2*)&Bb[c * PITCH + off];
                bf[nt][0] = b2.x; bf[nt][1] = b2.y;
            }
#pragma unroll
            for (int mt = 0; mt < 4; mt++)
#pragma unroll
                for (int nt = 0; nt < 8; nt++)
                    mma_tf32(acc[mt][nt], af[mt], bf[nt]);
        }
    }

    // ---- epilogue ----
#pragma unroll
    for (int nt = 0; nt < 8; nt++) {
        int jc = bn * 64 + nt * 8 + (lane & 3) * 2;
        float2 bb = *(const float2*)&bias[jc];
#pragma unroll
        for (int mt = 0; mt < 4; mt++) {
#pragma unroll
            for (int h = 0; h < 2; h++) {
                int m = bm * 256 + wid * 64 + mt * 16 + (lane >> 2) + h * 8;
                float2 v = { acc[mt][nt][2 * h + 0] + bb.x,
                             acc[mt][nt][2 * h + 1] + bb.y };
                if (MODE == 0) {
                    *(float2*)&g_qkv[(size_t)m * QKV_N + jc] = v;
                } else {
                    int w = m / NW, n = m % NW;
                    int b  = w >> 6;
                    int wr = (w & 63) >> 3;
                    int wc = w & 7;
                    int r  = wr * WS + n / WS;
                    int c  = wc * WS + n % WS;
                    size_t t = (size_t)b * 3136 + (size_t)r * HW + c;
                    *(float2*)&out[t * CCH + jc] = v;
                }
            }
        }
    }
}

// ---------------------------------------------------------------------------
// Kernel 3: tensor-core attention per (window, head). 128 threads = 4 warps.
// Output written tf32 k-permuted into g_att.
// ---------------------------------------------------------------------------
#define QKP 40
#define PP  72
#define NPQ 64
#define NPK 56
#define NT  7

__global__ void __launch_bounds__(128) attn_kernel(const float* __restrict__ rpb) {
    int w    = blockIdx.x;
    int head = blockIdx.y;
    int tid  = threadIdx.x;
    int lane = tid & 31;
    int wid  = tid >> 5;

    __shared__ uint32_t qkS[(NPQ + NPK) * QKP];
    __shared__ uint32_t vS[NPK * QKP];
    __shared__ float biasS[169];
    uint32_t* qS = qkS;
    uint32_t* kS = qkS + NPQ * QKP;
    uint32_t* pS = qkS;

    const float* qg = g_qkv + (size_t)w * NW * QKV_N + head * DH;
    const float* kg = qg + CCH;
    const float* vg = qg + 2 * CCH;

    const float scale = 0.17677669529663687f;

    {
        int row = tid >> 1;
        int c0  = (tid & 1) * 16;
        if (row < NW) {
            const float* qr = qg + (size_t)row * QKV_N;
#pragma unroll
            for (int j = 0; j < 4; j++) {
                float4 f = *(const float4*)(qr + c0 + j * 4);
                uint4 u = { f2tf32(f.x * scale), f2tf32(f.y * scale),
                            f2tf32(f.z * scale), f2tf32(f.w * scale) };
                *(uint4*)&qS[row * QKP + c0 + j * 4] = u;
            }
            const float* kr = kg + (size_t)row * QKV_N;
            const float* vr = vg + (size_t)row * QKV_N;
#pragma unroll
            for (int j = 0; j < 4; j++) {
                float4 f = *(const float4*)(kr + c0 + j * 4);
                uint4 u = { f2tf32(f.x), f2tf32(f.y), f2tf32(f.z), f2tf32(f.w) };
                *(uint4*)&kS[row * QKP + c0 + j * 4] = u;
                float4 g = *(const float4*)(vr + c0 + j * 4);
                uint4 uv = { f2tf32(g.x), f2tf32(g.y), f2tf32(g.z), f2tf32(g.w) };
                *(uint4*)&vS[row * QKP + c0 + j * 4] = uv;
            }
        } else {
            uint4 z = { 0, 0, 0, 0 };
#pragma unroll
            for (int j = 0; j < 4; j++)
                *(uint4*)&qS[row * QKP + c0 + j * 4] = z;
            if (row < NPK) {
#pragma unroll
                for (int j = 0; j < 4; j++) {
                    *(uint4*)&kS[row * QKP + c0 + j * 4] = z;
                    *(uint4*)&vS[row * QKP + c0 + j * 4] = z;
                }
            }
        }
    }
    for (int i = tid; i < 169; i += 128) biasS[i] = rpb[i * HEADS + head];
    __syncthreads();

    int m0 = wid * 16;
    float acc[NT][4] = {};
#pragma unroll
    for (int ks = 0; ks < DH; ks += 8) {
        uint32_t af[4];
        int row = m0 + (lane >> 2);
        int kk  = ks + (lane & 3);
        af[0] = qS[row * QKP + kk];
        af[1] = qS[(row + 8) * QKP + kk];
        af[2] = qS[row * QKP + kk + 4];
        af[3] = qS[(row + 8) * QKP + kk + 4];
#pragma unroll
        for (int nt = 0; nt < NT; nt++) {
            uint32_t bf[2];
            int col = nt * 8 + (lane >> 2);
            bf[0] = kS[col * QKP + kk];
            bf[1] = kS[col * QKP + kk + 4];
            mma_tf32(acc[nt], af, bf);
        }
    }

    int r0 = m0 + (lane >> 2);
    int r1 = r0 + 8;
    int r0c = r0 < NW ? r0 : NW - 1;
    int r1c = r1 < NW ? r1 : NW - 1;
    int ir0 = r0c / WS, ic0 = r0c % WS;
    int ir1 = r1c / WS, ic1 = r1c % WS;

    float mx0 = -1e30f, mx1 = -1e30f;
#pragma unroll
    for (int nt = 0; nt < NT; nt++) {
#pragma unroll
        for (int p = 0; p < 2; p++) {
            int col = nt * 8 + (lane & 3) * 2 + p;
            if (col < NW) {
                int jr = col / WS, jc = col % WS;
                acc[nt][p]     += biasS[(ir0 - jr + 6) * 13 + (ic0 - jc + 6)];
                acc[nt][2 + p] += biasS[(ir1 - jr + 6) * 13 + (ic1 - jc + 6)];
                mx0 = fmaxf(mx0, acc[nt][p]);
                mx1 = fmaxf(mx1, acc[nt][2 + p]);
            } else {
                acc[nt][p]     = -1e30f;
                acc[nt][2 + p] = -1e30f;
            }
        }
    }
    mx0 = fmaxf(mx0, __shfl_xor_sync(0xFFFFFFFFu, mx0, 1));
    mx0 = fmaxf(mx0, __shfl_xor_sync(0xFFFFFFFFu, mx0, 2));
    mx1 = fmaxf(mx1, __shfl_xor_sync(0xFFFFFFFFu, mx1, 1));
    mx1 = fmaxf(mx1, __shfl_xor_sync(0xFFFFFFFFu, mx1, 2));

    float sum0 = 0.f, sum1 = 0.f;
#pragma unroll
    for (int nt = 0; nt < NT; nt++) {
#pragma unroll
        for (int p = 0; p < 2; p++) {
            int col = nt * 8 + (lane & 3) * 2 + p;
            float e0 = (col < NW) ? __expf(acc[nt][p] - mx0) : 0.f;
            float e1 = (col < NW) ? __expf(acc[nt][2 + p] - mx1) : 0.f;
            acc[nt][p] = e0;
            acc[nt][2 + p] = e1;
            sum0 += e0;
            sum1 += e1;
        }
    }
    sum0 += __shfl_xor_sync(0xFFFFFFFFu, sum0, 1);
    sum0 += __shfl_xor_sync(0xFFFFFFFFu, sum0, 2);
    sum1 += __shfl_xor_sync(0xFFFFFFFFu, sum1, 1);
    sum1 += __shfl_xor_sync(0xFFFFFFFFu, sum1, 2);
    float inv0 = 1.0f / sum0;
    float inv1 = 1.0f / sum1;

    __syncthreads();

#pragma unroll
    for (int nt = 0; nt < NT; nt++) {
        int col = nt * 8 + (lane & 3) * 2;
        uint2 v0 = { f2tf32(acc[nt][0] * inv0), f2tf32(acc[nt][1] * inv0) };
        uint2 v1 = { f2tf32(acc[nt][2] * inv1), f2tf32(acc[nt][3] * inv1) };
        *(uint2*)&pS[r0 * PP + col] = v0;
        *(uint2*)&pS[r1 * PP + col] = v1;
    }
    __syncthreads();

    float acc2[4][4] = {};
#pragma unroll
    for (int ks = 0; ks < NPK; ks += 8) {
        uint32_t af[4];
        int row = m0 + (lane >> 2);
        int kk  = ks + (lane & 3);
        af[0] = pS[row * PP + kk];
        af[1] = pS[(row + 8) * PP + kk];
        af[2] = pS[row * PP + kk + 4];
        af[3] = pS[(row + 8) * PP + kk + 4];
#pragma unroll
        for (int nt = 0; nt < 4; nt++) {
            uint32_t bf[2];
            int col = nt * 8 + (lane >> 2);
            bf[0] = vS[kk * QKP + col];
            bf[1] = vS[(kk + 4) * QKP + col];
            mma_tf32(acc2[nt], af, bf);
        }
    }

    // store tf32 k-permuted into g_att (slab = head since DH == 32)
    uint32_t* outp = g_att + (size_t)w * NW * CCH + head * DH;
#pragma unroll
    for (int nt = 0; nt < 4; nt++) {
        int col = nt * 8 + (lane & 3) * 2;
        int pA = pos32(col);
        int pB = pos32(col + 1);
        if (r0 < NW) {
            outp[(size_t)r0 * CCH + pA] = f2tf32(acc2[nt][0]);
            outp[(size_t)r0 * CCH + pB] = f2tf32(acc2[nt][1]);
        }
        if (r1 < NW) {
            outp[(size_t)r1 * CCH + pA] = f2tf32(acc2[nt][2]);
            outp[(size_t)r1 * CCH + pB] = f2tf32(acc2[nt][3]);
        }
    }
}

// ---------------------------------------------------------------------------
extern "C" void kernel_launch(void* const* d_in, const int* in_sizes, int n_in,
                              void* d_out, int out_size) {
    const float* x      = (const float*)d_in[0];
    const float* gamma  = (const float*)d_in[1];
    const float* rpb    = (const float*)d_in[2];
    const float* qkv_w  = (const float*)d_in[3];
    const float* qkv_b  = (const float*)d_in[4];
    const float* proj_w = (const float*)d_in[5];
    const float* proj_b = (const float*)d_in[6];
    float* out = (float*)d_out;

    uint32_t *xw_p, *att_p, *wq_p, *wp_p;
    cudaGetSymbolAddress((void**)&xw_p,  g_xw);
    cudaGetSymbolAddress((void**)&att_p, g_att);
    cudaGetSymbolAddress((void**)&wq_p,  g_wq);
    cudaGetSymbolAddress((void**)&wp_p,  g_wp);

    cudaFuncSetAttribute(gemm_tc_kernel<0>, cudaFuncAttributeMaxDynamicSharedMemorySize, GSMEM);
    cudaFuncSetAttribute(gemm_tc_kernel<1>, cudaFuncAttributeMaxDynamicSharedMemorySize, GSMEM);

    prep_w_kernel<<<(QKV_N * CCH + 255) / 256, 256>>>(qkv_w, wq_p, QKV_N * CCH);
    prep_w_kernel<<<(CCH * CCH + 255) / 256, 256>>>(proj_w, wp_p, CCH * CCH);
    ln_kernel<<<MTOK / 8, 256>>>(x, gamma);
    gemm_tc_kernel<0><<<dim3(QKV_N / 64, MTOK / 256), 128, GSMEM>>>(xw_p, wq_p, qkv_b, nullptr);
    attn_kernel<<<dim3(NWIN, HEADS), 128>>>(rpb);
    gemm_tc_kernel<1><<<dim3(CCH / 64, MTOK / 256), 128, GSMEM>>>(att_p, wp_p, proj_b, out);
}

// round 9
// speedup vs baseline: 3.1822x; 1.5270x over previous
#include <cuda_runtime.h>
#include <cuda_fp16.h>
#include <cstdint>

#define BATCH   32
#define HW      56
#define CCH     192
#define WS      7
#define NW      49
#define NWIN    2048
#define HEADS   6
#define DH      32
#define MTOK    100352
#define QKV_N   576
#define CW      96          // half2 words per 192-k row
#define QW      288         // half2 words per 576-k row

// Scratch (device globals — allocation-free). fp16 operands, k-permuted.
__device__ uint32_t g_xw[(size_t)MTOK * CW];           // LN'd x, window order
__device__ uint32_t g_qkv[(size_t)(MTOK + 8) * QW];    // qkv, +8 pad rows (zeroed)
__device__ uint32_t g_att[(size_t)MTOK * CW];          // attn out
__device__ uint32_t g_wq[(size_t)QKV_N * CW];
__device__ uint32_t g_wp[(size_t)CCH * CW];

// permutation within a 16-k slab of 8 half2 words: slot = ((h&3)<<1)|(h>>2)
__device__ __forceinline__ int pos8(int h) { return ((h & 3) << 1) | (h >> 2); }

__device__ __forceinline__ void mma_f16(float c[4], const uint32_t a[4], const uint32_t b[2]) {
    asm volatile(
        "mma.sync.aligned.m16n8k16.row.col.f32.f16.f16.f32 "
        "{%0,%1,%2,%3}, {%4,%5,%6,%7}, {%8,%9}, {%0,%1,%2,%3};"
        : "+f"(c[0]), "+f"(c[1]), "+f"(c[2]), "+f"(c[3])
        : "r"(a[0]), "r"(a[1]), "r"(a[2]), "r"(a[3]), "r"(b[0]), "r"(b[1]));
}
__device__ __forceinline__ uint32_t smem_u32(const void* p) {
    uint32_t a;
    asm("{ .reg .u64 t; cvta.to.shared.u64 t, %1; cvt.u32.u64 %0, t; }" : "=r"(a) : "l"(p));
    return a;
}
__device__ __forceinline__ void cp16(uint32_t s, const void* g) {
    asm volatile("cp.async.cg.shared.global [%0], [%1], 16;" :: "r"(s), "l"(g));
}
#define CP_COMMIT() asm volatile("cp.async.commit_group;" ::: "memory")
#define CP_WAIT0()  asm volatile("cp.async.wait_group 0;" ::: "memory")

__device__ __forceinline__ uint32_t pack_h2(float a, float b) {
    __half2 h = __floats2half2_rn(a, b);
    return *(uint32_t*)&h;
}

// ---------------------------------------------------------------------------
// Kernel A: zero the g_qkv pad rows (8 x 288 words).
// ---------------------------------------------------------------------------
__global__ void zero_pad_kernel() {
    int i = blockIdx.x * 256 + threadIdx.x;
    if (i < 8 * QW) g_qkv[(size_t)MTOK * QW + i] = 0;
}

// ---------------------------------------------------------------------------
// Kernel B: weight prep — fp16 convert + permute. One thread per k-pair.
// ---------------------------------------------------------------------------
__global__ void prep_w_kernel(const float* __restrict__ src, uint32_t* __restrict__ dst, int npair) {
    int idx = blockIdx.x * 256 + threadIdx.x;
    if (idx < npair) {
        int r = idx / CW, p = idx % CW;
        float2 f = *(const float2*)(src + (size_t)r * CCH + 2 * p);
        dst[(size_t)r * CW + (p & ~7) + pos8(p & 7)] = pack_h2(f.x, f.y);
    }
}

// ---------------------------------------------------------------------------
// Kernel 1: LayerNorm + window partition + fp16 convert + permute.
// ---------------------------------------------------------------------------
__global__ void ln_kernel(const float* __restrict__ x, const float* __restrict__ gamma) {
    int t    = blockIdx.x * 8 + (threadIdx.x >> 5);
    int lane = threadIdx.x & 31;
    const float* xp = x + (size_t)t * CCH;

    float2 v[3], g[3];
    float s = 0.f, sq = 0.f;
#pragma unroll
    for (int i = 0; i < 3; i++) {
        int p = lane + 32 * i;
        v[i] = *(const float2*)(xp + 2 * p);
        g[i] = *(const float2*)(gamma + 2 * p);
        s  += v[i].x + v[i].y;
        sq += v[i].x * v[i].x + v[i].y * v[i].y;
    }
#pragma unroll
    for (int off = 16; off > 0; off >>= 1) {
        s  += __shfl_xor_sync(0xFFFFFFFFu, s,  off);
        sq += __shfl_xor_sync(0xFFFFFFFFu, sq, off);
    }
    float mu  = s * (1.0f / CCH);
    float var = sq * (1.0f / CCH) - mu * mu;
    float rs  = rsqrtf(var + 1e-5f);

    int b  = t / 3136;
    int rc = t % 3136;
    int r  = rc / HW, c = rc % HW;
    int w  = (b * 8 + r / WS) * 8 + c / WS;
    int n  = (r % WS) * WS + (c % WS);

    uint32_t* dst = g_xw + ((size_t)w * NW + n) * CW;
#pragma unroll
    for (int i = 0; i < 3; i++) {
        int p = lane + 32 * i;
        dst[(p & ~7) + pos8(p & 7)] =
            pack_h2((v[i].x - mu) * rs * g[i].x, (v[i].y - mu) * rs * g[i].y);
    }
}

// ---------------------------------------------------------------------------
// FP16 GEMM: BM=256, BN=64, BK=32. 128 threads = 4 warps, warp tile 64x64.
// ---------------------------------------------------------------------------
#define PITCH  24
#define AWRD   (256 * PITCH)
#define BWRD   (64 * PITCH)
#define BUFWRD (AWRD + BWRD)
#define GSMEM  (2 * BUFWRD * 4)     // 61440 bytes

template <int MODE>
__global__ void __launch_bounds__(128) gemm_f16_kernel(const uint32_t* __restrict__ A,
                                                       const uint32_t* __restrict__ Wt,
                                                       const float* __restrict__ bias,
                                                       float* __restrict__ out) {
    extern __shared__ uint32_t sm[];
    uint32_t sb = smem_u32(sm);

    int tid  = threadIdx.x;
    int lane = tid & 31;
    int wid  = tid >> 5;
    int bn = blockIdx.x;
    int bm = blockIdx.y;

    const uint32_t* Ag = A  + (size_t)(bm * 256) * CW;
    const uint32_t* Bg = Wt + (size_t)(bn * 64) * CW;

    float acc[4][8][4] = {};

    // tile 0
    {
#pragma unroll
        for (int i = 0; i < 8; i++) {
            int q = i * 128 + tid;
            int row = q >> 2, sr = q & 3;
            cp16(sb + (row * PITCH + sr * 4) * 4, Ag + (size_t)row * CW + sr * 4);
        }
#pragma unroll
        for (int i = 0; i < 2; i++) {
            int q = i * 128 + tid;
            int row = q >> 2, sr = q & 3;
            cp16(sb + (AWRD + row * PITCH + sr * 4) * 4, Bg + (size_t)row * CW + sr * 4);
        }
        CP_COMMIT();
    }

#pragma unroll
    for (int kt = 0; kt < 6; kt++) {
        CP_WAIT0();
        __syncthreads();

        if (kt < 5) {
            int buf = (kt + 1) & 1;
            int ko  = (kt + 1) * 16;
            uint32_t ab = sb + buf * BUFWRD * 4;
#pragma unroll
            for (int i = 0; i < 8; i++) {
                int q = i * 128 + tid;
                int row = q >> 2, sr = q & 3;
                cp16(ab + (row * PITCH + sr * 4) * 4, Ag + (size_t)row * CW + ko + sr * 4);
            }
#pragma unroll
            for (int i = 0; i < 2; i++) {
                int q = i * 128 + tid;
                int row = q >> 2, sr = q & 3;
                cp16(ab + (AWRD + row * PITCH + sr * 4) * 4, Bg + (size_t)row * CW + ko + sr * 4);
            }
            CP_COMMIT();
        }

        const uint32_t* Ab = sm + (kt & 1) * BUFWRD;
        const uint32_t* Bb = Ab + AWRD;
#pragma unroll
        for (int ks = 0; ks < 2; ks++) {
            int off = ks * 8 + 2 * (lane & 3);
            uint32_t af[4][4];
            uint32_t bf[8][2];
#pragma unroll
            for (int mt = 0; mt < 4; mt++) {
                int r = wid * 64 + mt * 16 + (lane >> 2);
                uint2 lo = *(const uint2*)&Ab[r * PITCH + off];
                uint2 hi = *(const uint2*)&Ab[(r + 8) * PITCH + off];
                af[mt][0] = lo.x; af[mt][2] = lo.y;
                af[mt][1] = hi.x; af[mt][3] = hi.y;
            }
#pragma unroll
            for (int nt = 0; nt < 8; nt++) {
                int c = nt * 8 + (lane >> 2);
                uint2 b2 = *(const uint2*)&Bb[c * PITCH + off];
                bf[nt][0] = b2.x; bf[nt][1] = b2.y;
            }
#pragma unroll
            for (int mt = 0; mt < 4; mt++)
#pragma unroll
                for (int nt = 0; nt < 8; nt++)
                    mma_f16(acc[mt][nt], af[mt], bf[nt]);
        }
    }

    // epilogue
#pragma unroll
    for (int nt = 0; nt < 8; nt++) {
        int jc = bn * 64 + nt * 8 + (lane & 3) * 2;
        float2 bb = *(const float2*)&bias[jc];
        int gword = (jc >> 4) * 8 + pos8((jc & 15) >> 1);
#pragma unroll
        for (int mt = 0; mt < 4; mt++) {
#pragma unroll
            for (int h = 0; h < 2; h++) {
                int m = bm * 256 + wid * 64 + mt * 16 + (lane >> 2) + h * 8;
                float vx = acc[mt][nt][2 * h + 0] + bb.x;
                float vy = acc[mt][nt][2 * h + 1] + bb.y;
                if (MODE == 0) {
                    g_qkv[(size_t)m * QW + gword] = pack_h2(vx, vy);
                } else {
                    int w = m / NW, n = m % NW;
                    int b  = w >> 6;
                    int wr = (w & 63) >> 3;
                    int wc = w & 7;
                    int r  = wr * WS + n / WS;
                    int c  = wc * WS + n % WS;
                    size_t t = (size_t)b * 3136 + (size_t)r * HW + c;
                    float2 v = { vx, vy };
                    *(float2*)&out[t * CCH + jc] = v;
                }
            }
        }
    }
}

// ---------------------------------------------------------------------------
// Kernel 3: fp16 attention per (window, head). P has its own pitch-40 buffer.
// ---------------------------------------------------------------------------
#define QKP2  24      // pitch for q/k rows (16 data words)
#define PP2   40      // pitch for P rows (32 data words)
#define VTP   40      // pitch for V^T rows (32 data words)
#define NT    7

__global__ void __launch_bounds__(128) attn_kernel(const float* __restrict__ rpb) {
    int w    = blockIdx.x;
    int head = blockIdx.y;
    int tid  = threadIdx.x;
    int lane = tid & 31;
    int wid  = tid >> 5;

    __shared__ uint32_t qS[64 * QKP2];
    __shared__ uint32_t kS[56 * QKP2];
    __shared__ uint32_t pS[64 * PP2];
    __shared__ uint32_t vT[32 * VTP];
    __shared__ float biasS[169];
    uint32_t sqb = smem_u32(qS);
    uint32_t skb = smem_u32(kS);

    size_t mbase = (size_t)w * NW;

    // q/k: 56 rows x 4 segs each = 448 cp16
#pragma unroll
    for (int i = 0; i < 4; i++) {
        int s = i * 128 + tid;
        if (s < 448) {
            int isk = s >= 224;
            int ss  = s - isk * 224;
            int row = ss >> 2, sr = ss & 3;
            const uint32_t* src = g_qkv + (mbase + row) * QW + isk * 96 + head * 16 + sr * 4;
            uint32_t dst = (isk ? skb : sqb) + (row * QKP2 + sr * 4) * 4;
            cp16(dst, src);
        }
    }
    CP_COMMIT();

    // zero q rows 56..63
    if (tid < 64) {
        int row = 56 + (tid >> 3);
        uint2 z = { 0, 0 };
        *(uint2*)&qS[row * QKP2 + (tid & 7) * 2] = z;
    }
    // zero vT token slots 56..63 (words 25,27,29,31 per dh row)
    {
        int dh = tid >> 2;
        vT[dh * VTP + 25 + (tid & 3) * 2] = 0;
    }
    // V transpose: 56 rows x 16 words
#pragma unroll
    for (int i = 0; i < 7; i++) {
        int s = i * 128 + tid;
        int row = s >> 4, word = s & 15;
        uint32_t u = g_qkv[(mbase + row) * QW + 192 + head * 16 + word];
        int slab = word >> 3, slot = word & 7;
        int hh = (slot >> 1) | ((slot & 1) << 2);
        int dh = slab * 16 + hh * 2;
        int tslab = row >> 4;
        int tword = tslab * 8 + pos8((row & 15) >> 1);
        __half* vp = (__half*)vT;
        __half2 hv = *(__half2*)&u;
        vp[dh * (2 * VTP) + tword * 2 + (row & 1)]       = __low2half(hv);
        vp[(dh + 1) * (2 * VTP) + tword * 2 + (row & 1)] = __high2half(hv);
    }
    for (int i = tid; i < 169; i += 128) biasS[i] = rpb[i * HEADS + head];
    CP_WAIT0();
    __syncthreads();

    const float scale = 0.17677669529663687f;  // 1/sqrt(32)

    // ---- QK^T ----
    int m0 = wid * 16;
    float acc[NT][4] = {};
#pragma unroll
    for (int ks = 0; ks < 2; ks++) {
        int off = ks * 8 + 2 * (lane & 3);
        uint32_t af[4];
        int row = m0 + (lane >> 2);
        uint2 lo = *(const uint2*)&qS[row * QKP2 + off];
        uint2 hi = *(const uint2*)&qS[(row + 8) * QKP2 + off];
        af[0] = lo.x; af[2] = lo.y;
        af[1] = hi.x; af[3] = hi.y;
#pragma unroll
        for (int nt = 0; nt < NT; nt++) {
            int c = nt * 8 + (lane >> 2);
            uint2 b2 = *(const uint2*)&kS[c * QKP2 + off];
            uint32_t bf[2] = { b2.x, b2.y };
            mma_f16(acc[nt], af, bf);
        }
    }

    // ---- scale + bias + masked softmax ----
    int r0 = m0 + (lane >> 2);
    int r1 = r0 + 8;
    int r0c = r0 < NW ? r0 : NW - 1;
    int r1c = r1 < NW ? r1 : NW - 1;
    int ir0 = r0c / WS, ic0 = r0c % WS;
    int ir1 = r1c / WS, ic1 = r1c % WS;

    float mx0 = -1e30f, mx1 = -1e30f;
#pragma unroll
    for (int nt = 0; nt < NT; nt++) {
#pragma unroll
        for (int p = 0; p < 2; p++) {
            int col = nt * 8 + (lane & 3) * 2 + p;
            if (col < NW) {
                int jr = col / WS, jc = col % WS;
                acc[nt][p]     = acc[nt][p]     * scale + biasS[(ir0 - jr + 6) * 13 + (ic0 - jc + 6)];
                acc[nt][2 + p] = acc[nt][2 + p] * scale + biasS[(ir1 - jr + 6) * 13 + (ic1 - jc + 6)];
                mx0 = fmaxf(mx0, acc[nt][p]);
                mx1 = fmaxf(mx1, acc[nt][2 + p]);
            } else {
                acc[nt][p]     = -1e30f;
                acc[nt][2 + p] = -1e30f;
            }
        }
    }
    mx0 = fmaxf(mx0, __shfl_xor_sync(0xFFFFFFFFu, mx0, 1));
    mx0 = fmaxf(mx0, __shfl_xor_sync(0xFFFFFFFFu, mx0, 2));
    mx1 = fmaxf(mx1, __shfl_xor_sync(0xFFFFFFFFu, mx1, 1));
    mx1 = fmaxf(mx1, __shfl_xor_sync(0xFFFFFFFFu, mx1, 2));

    float sum0 = 0.f, sum1 = 0.f;
#pragma unroll
    for (int nt = 0; nt < NT; nt++) {
#pragma unroll
        for (int p = 0; p < 2; p++) {
            int col = nt * 8 + (lane & 3) * 2 + p;
            float e0 = (col < NW) ? __expf(acc[nt][p] - mx0) : 0.f;
            float e1 = (col < NW) ? __expf(acc[nt][2 + p] - mx1) : 0.f;
            acc[nt][p] = e0;
            acc[nt][2 + p] = e1;
            sum0 += e0;
            sum1 += e1;
        }
    }
    sum0 += __shfl_xor_sync(0xFFFFFFFFu, sum0, 1);
    sum0 += __shfl_xor_sync(0xFFFFFFFFu, sum0, 2);
    sum1 += __shfl_xor_sync(0xFFFFFFFFu, sum1, 1);
    sum1 += __shfl_xor_sync(0xFFFFFFFFu, sum1, 2);
    float inv0 = 1.0f / sum0;
    float inv1 = 1.0f / sum1;

    // store P permuted (pitch PP2); zero cols 56..63 (slab 3)
#pragma unroll
    for (int nt = 0; nt < NT; nt++) {
        int col = nt * 8 + (lane & 3) * 2;
        int wI = (col >> 4) * 8 + pos8((col & 15) >> 1);
        pS[r0 * PP2 + wI] = pack_h2(acc[nt][0] * inv0, acc[nt][1] * inv0);
        pS[r1 * PP2 + wI] = pack_h2(acc[nt][2] * inv1, acc[nt][3] * inv1);
    }
    {
        int wZ = 24 + pos8(4 + (lane & 3));
        pS[r0 * PP2 + wZ] = 0;
        pS[r1 * PP2 + wZ] = 0;
    }
    __syncthreads();

    // ---- AV: rows m0..m0+15 x dh 0..31, K = 64 tokens (4 k16 steps) ----
    float acc2[4][4] = {};
#pragma unroll
    for (int ks = 0; ks < 4; ks++) {
        int off = ks * 8 + 2 * (lane & 3);
        uint32_t af[4];
        int row = m0 + (lane >> 2);
        uint2 lo = *(const uint2*)&pS[row * PP2 + off];
        uint2 hi = *(const uint2*)&pS[(row + 8) * PP2 + off];
        af[0] = lo.x; af[2] = lo.y;
        af[1] = hi.x; af[3] = hi.y;
#pragma unroll
        for (int nt = 0; nt < 4; nt++) {
            int c = nt * 8 + (lane >> 2);
            uint2 b2 = *(const uint2*)&vT[c * VTP + off];
            uint32_t bf[2] = { b2.x, b2.y };
            mma_f16(acc2[nt], af, bf);
        }
    }

    // store permuted fp16 into g_att
    uint32_t* outp = g_att + (mbase)*CW;
#pragma unroll
    for (int nt = 0; nt < 4; nt++) {
        int c = nt * 8 + (lane & 3) * 2;      // dh pair
        int kk = head * DH + c;
        int gw = (kk >> 4) * 8 + pos8((kk & 15) >> 1);
        if (r0 < NW) outp[(size_t)r0 * CW + gw] = pack_h2(acc2[nt][0], acc2[nt][1]);
        if (r1 < NW) outp[(size_t)r1 * CW + gw] = pack_h2(acc2[nt][2], acc2[nt][3]);
    }
}

// ---------------------------------------------------------------------------
extern "C" void kernel_launch(void* const* d_in, const int* in_sizes, int n_in,
                              void* d_out, int out_size) {
    const float* x      = (const float*)d_in[0];
    const float* gamma  = (const float*)d_in[1];
    const float* rpb    = (const float*)d_in[2];
    const float* qkv_w  = (const float*)d_in[3];
    const float* qkv_b  = (const float*)d_in[4];
    const float* proj_w = (const float*)d_in[5];
    const float* proj_b = (const float*)d_in[6];
    float* out = (float*)d_out;

    uint32_t *xw_p, *att_p, *wq_p, *wp_p;
    cudaGetSymbolAddress((void**)&xw_p,  g_xw);
    cudaGetSymbolAddress((void**)&att_p, g_att);
    cudaGetSymbolAddress((void**)&wq_p,  g_wq);
    cudaGetSymbolAddress((void**)&wp_p,  g_wp);

    cudaFuncSetAttribute(gemm_f16_kernel<0>, cudaFuncAttributeMaxDynamicSharedMemorySize, GSMEM);
    cudaFuncSetAttribute(gemm_f16_kernel<1>, cudaFuncAttributeMaxDynamicSharedMemorySize, GSMEM);

    zero_pad_kernel<<<9, 256>>>();
    prep_w_kernel<<<(QKV_N * CW + 255) / 256, 256>>>(qkv_w, wq_p, QKV_N * CW);
    prep_w_kernel<<<(CCH * CW + 255) / 256, 256>>>(proj_w, wp_p, CCH * CW);
    ln_kernel<<<MTOK / 8, 256>>>(x, gamma);
    gemm_f16_kernel<0><<<dim3(QKV_N / 64, MTOK / 256), 128, GSMEM>>>(xw_p, wq_p, qkv_b, nullptr);
    attn_kernel<<<dim3(NWIN, HEADS), 128>>>(rpb);
    gemm_f16_kernel<1><<<dim3(CCH / 64, MTOK / 256), 128, GSMEM>>>(att_p, wp_p, proj_b, out);
}